// round 9
// baseline (speedup 1.0000x reference)
#include <cuda_runtime.h>
#include <cuda_bf16.h>

// InvertiblePWL, persistent single-wave kernel, BANK-REPLICATED table:
//   out = eps * A[idx] + B[idx]
//   idx via magic-number floor: clamp e to [-5.05, 5.0],
//     r1 = fma.rm(e, 9.9, 49.5); r2 = add.rm(r1, 12582912.0);
//     idx = float_bits(r2) - 1262485503   in [0, 100]
// Table stored 32x replicated: rep[idx*32 + lane] -> byte addr idx*256+lane*8,
// so lane l always hits bank pair 2l => conflict-free LDS.64 for ANY index mix.

#define N_BINS 100
#define NTAB   (N_BINS + 1)      // 101
#define TPB    256
#define GRID   1184              // 8 CTAs/SM * 148 SMs -> one persistent wave

__global__ void __launch_bounds__(TPB)
pwl_kernel(const float4* __restrict__ eps,
           const float*  __restrict__ p,
           const float*  __restrict__ b,
           const float*  __restrict__ points,
           float4* __restrict__ out, int n4) {
    __shared__ float2 sCompact[NTAB];        // staging (808 B)
    __shared__ float2 sRep[NTAB * 32];       // 32-way replicated (25856 B)

    const int t = threadIdx.x;
    const int lane = t & 31;

    // ---- Warp 0: build compact table. Lane l owns indices 4l..4l+3.
    if (t < 32) {
        const float int_len = 10.0f / 99.0f;
        const int i0 = 4 * t;
        const float b0 = b[0];

        float pv[4], pts[4];
#pragma unroll
        for (int k = 0; k < 4; k++) {
            const int idx = i0 + k;
            pv[k]  = (idx <= N_BINS) ? p[idx] : 0.0f;
            const int s = (idx > 0) ? (idx - 1) : 0;
            pts[k] = (idx <= N_BINS) ? points[s] : 0.0f;
        }

        float a[4], d[4];
#pragma unroll
        for (int k = 0; k < 4; k++) {
            const int idx = i0 + k;
            a[k] = expf(pv[k]) + 0.001f;
            d[k] = (idx >= 1 && idx <= N_BINS - 1) ? int_len * a[k] : 0.0f;
        }

        float l1 = d[0] + d[1];
        float lsum = l1 + d[2] + d[3];

        float incl = lsum;
#pragma unroll
        for (int o = 1; o < 32; o <<= 1) {
            float u = __shfl_up_sync(0xFFFFFFFFu, incl, o);
            if (t >= o) incl += u;
        }
        const float lane_excl = incl - lsum;

        float ex[4];
        ex[0] = lane_excl;
        ex[1] = lane_excl + d[0];
        ex[2] = lane_excl + l1;
        ex[3] = lane_excl + l1 + d[2];

#pragma unroll
        for (int k = 0; k < 4; k++) {
            const int idx = i0 + k;
            if (idx <= N_BINS)
                sCompact[idx] = make_float2(a[k], (b0 + ex[k]) - pts[k] * a[k]);
        }
    }

    // ---- Prefetch first two elements (in flight across both barriers).
    const int stride = GRID * TPB;
    int i0 = blockIdx.x * TPB + t;
    int i1 = i0 + stride;
    float4 cur, nxt;
    if (i0 < n4) cur = eps[i0];
    if (i1 < n4) nxt = eps[i1];

    __syncthreads();

    // ---- Replicate 32x: thread t writes entries for its own lane's bank pair
    // (addr = i*256 + (t&31)*8 -> bank 2*(t&31): conflict-free). Reads of
    // sCompact[i] are warp-broadcast (same i across the warp).
    for (int j = t; j < NTAB * 32; j += TPB) {
        const int i = j >> 5;
        const int l = j & 31;
        sRep[i * 32 + l] = sCompact[i];
    }
    __syncthreads();

    const float2* __restrict__ myTab = sRep + lane;   // lane-private bank pair
    const float inv_len = 99.0f / 10.0f;

    // ---- Pipelined grid-stride loop: always two loads in flight.
    while (i0 < n4) {
        const int i2 = i1 + stride;
        float4 fut;
        if (i2 < n4) fut = eps[i2];

        float4 r;
        {
            const float ec = fminf(fmaxf(cur.x, -5.05f), 5.0f);
            const float r2 = __fadd_rd(__fmaf_rd(ec, inv_len, 49.5f), 12582912.0f);
            const int idx = __float_as_int(r2) - 1262485503;
            const float2 ab = myTab[idx * 32];
            r.x = fmaf(cur.x, ab.x, ab.y);
        }
        {
            const float ec = fminf(fmaxf(cur.y, -5.05f), 5.0f);
            const float r2 = __fadd_rd(__fmaf_rd(ec, inv_len, 49.5f), 12582912.0f);
            const int idx = __float_as_int(r2) - 1262485503;
            const float2 ab = myTab[idx * 32];
            r.y = fmaf(cur.y, ab.x, ab.y);
        }
        {
            const float ec = fminf(fmaxf(cur.z, -5.05f), 5.0f);
            const float r2 = __fadd_rd(__fmaf_rd(ec, inv_len, 49.5f), 12582912.0f);
            const int idx = __float_as_int(r2) - 1262485503;
            const float2 ab = myTab[idx * 32];
            r.z = fmaf(cur.z, ab.x, ab.y);
        }
        {
            const float ec = fminf(fmaxf(cur.w, -5.05f), 5.0f);
            const float r2 = __fadd_rd(__fmaf_rd(ec, inv_len, 49.5f), 12582912.0f);
            const int idx = __float_as_int(r2) - 1262485503;
            const float2 ab = myTab[idx * 32];
            r.w = fmaf(cur.w, ab.x, ab.y);
        }
        out[i0] = r;

        cur = nxt;
        nxt = fut;
        i0 = i1;
        i1 = i2;
    }
}

extern "C" void kernel_launch(void* const* d_in, const int* in_sizes, int n_in,
                              void* d_out, int out_size) {
    const float* eps    = (const float*)d_in[0];   // [4000000]
    const float* p      = (const float*)d_in[1];   // [101]
    const float* b      = (const float*)d_in[2];   // [1]
    const float* points = (const float*)d_in[3];   // [100]
    float* out = (float*)d_out;

    const int n4 = out_size / 4;                   // 1,000,000
    pwl_kernel<<<GRID, TPB>>>((const float4*)eps, p, b, points,
                              (float4*)out, n4);
}

// round 10
// speedup vs baseline: 1.2704x; 1.2704x over previous
#include <cuda_runtime.h>
#include <cuda_bf16.h>

// InvertiblePWL, persistent kernel, WIDE CTAs (1024 thr, 296 CTAs = 2/SM):
//   out = eps * A[idx] + B[idx]
//   idx via magic-number floor: clamp e to [-5.05, 5.0],
//     r1 = fma.rm(e, 9.9, 49.5); r2 = add.rm(r1, 12582912.0);
//     idx = float_bits(r2) - 1262485503   in [0, 100]
//   A[i] = exp(p[i]) + 0.001
//   B[i] = (b0 + pref_excl[i]) - points[max(i-1,0)] * A[i]
// Same warp count as the best 256-thread config, but 4x fewer CTAs ->
// shorter launch ramp/drain and 4x fewer table-build prologues.

#define N_BINS 100
#define TPB    1024
#define GRID   296          // 2 CTAs/SM * 148 SMs; 296*1024 = 303104 threads

__device__ __forceinline__ float pwl_one(float e, const float2* __restrict__ sAB) {
    const float ec = fminf(fmaxf(e, -5.05f), 5.0f);
    const float r1 = __fmaf_rd(ec, 9.9f, 49.5f);
    const float r2 = __fadd_rd(r1, 12582912.0f);       // 1.5*2^23, ULP=1
    const int  idx = __float_as_int(r2) - 1262485503;  // floor(raw)+1 in [0,100]
    const float2 ab = sAB[idx];
    return fmaf(e, ab.x, ab.y);
}

__global__ void __launch_bounds__(TPB, 2)
pwl_kernel(const float4* __restrict__ eps,
           const float*  __restrict__ p,
           const float*  __restrict__ b,
           const float*  __restrict__ points,
           float4* __restrict__ out, int n4) {
    __shared__ float2 sAB[N_BINS + 1];

    const int t = threadIdx.x;

    // ---- Warp 0: build table. Lane l owns indices 4l..4l+3 (0..127).
    if (t < 32) {
        const float int_len = 10.0f / 99.0f;
        const int i0 = 4 * t;
        const float b0 = b[0];

        float pv[4], pts[4];
#pragma unroll
        for (int k = 0; k < 4; k++) {
            const int idx = i0 + k;
            pv[k]  = (idx <= N_BINS) ? p[idx] : 0.0f;
            const int s = (idx > 0) ? (idx - 1) : 0;
            pts[k] = (idx <= N_BINS) ? points[s] : 0.0f;
        }

        float a[4], d[4];
#pragma unroll
        for (int k = 0; k < 4; k++) {
            const int idx = i0 + k;
            a[k] = expf(pv[k]) + 0.001f;
            d[k] = (idx >= 1 && idx <= N_BINS - 1) ? int_len * a[k] : 0.0f;
        }

        float l1 = d[0] + d[1];
        float lsum = l1 + d[2] + d[3];

        float incl = lsum;
#pragma unroll
        for (int o = 1; o < 32; o <<= 1) {
            float u = __shfl_up_sync(0xFFFFFFFFu, incl, o);
            if (t >= o) incl += u;
        }
        const float lane_excl = incl - lsum;

        float ex[4];
        ex[0] = lane_excl;
        ex[1] = lane_excl + d[0];
        ex[2] = lane_excl + l1;
        ex[3] = lane_excl + l1 + d[2];

#pragma unroll
        for (int k = 0; k < 4; k++) {
            const int idx = i0 + k;
            if (idx <= N_BINS)
                sAB[idx] = make_float2(a[k], (b0 + ex[k]) - pts[k] * a[k]);
        }
    }

    // ---- Depth-2 prefetch before the barrier (hides table build).
    const int stride = GRID * TPB;
    int i0 = blockIdx.x * TPB + t;
    int i1 = i0 + stride;
    float4 cur, nxt;
    if (i0 < n4) cur = eps[i0];
    if (i1 < n4) nxt = eps[i1];

    __syncthreads();

    // ---- Pipelined grid-stride loop: always two loads in flight.
    while (i0 < n4) {
        const int i2 = i1 + stride;
        float4 fut;
        if (i2 < n4) fut = eps[i2];

        float4 r;
        r.x = pwl_one(cur.x, sAB);
        r.y = pwl_one(cur.y, sAB);
        r.z = pwl_one(cur.z, sAB);
        r.w = pwl_one(cur.w, sAB);
        out[i0] = r;

        cur = nxt;
        nxt = fut;
        i0 = i1;
        i1 = i2;
    }
}

extern "C" void kernel_launch(void* const* d_in, const int* in_sizes, int n_in,
                              void* d_out, int out_size) {
    const float* eps    = (const float*)d_in[0];   // [4000000]
    const float* p      = (const float*)d_in[1];   // [101]
    const float* b      = (const float*)d_in[2];   // [1]
    const float* points = (const float*)d_in[3];   // [100]
    float* out = (float*)d_out;

    const int n4 = out_size / 4;                   // 1,000,000
    pwl_kernel<<<GRID, TPB>>>((const float4*)eps, p, b, points,
                              (float4*)out, n4);
}